// round 12
// baseline (speedup 1.0000x reference)
#include <cuda_runtime.h>
#include <cuda_bf16.h>
#include <math.h>

#define NN 50000
#define NE 800000

// ---------------- device scratch ----------------
__device__ float g_xl1[NN * 128];
__device__ float g_xr1[NN * 128];
__device__ float g_h1 [NN * 128];
__device__ float g_xl2[NN * 64];
__device__ float g_xr2[NN * 64];
__device__ int   g_cnt[NN];
__device__ int   g_rowptr[NN + 1];
__device__ int   g_blocksum[64];
__device__ int   g_src[NE];
__device__ float g_ea [NE];

// ---------------- launch 1: zero counters + layer-1 projections ----------------
__global__ __launch_bounds__(128) void k_pre(const float* __restrict__ x,
                                             const float* __restrict__ Wl,
                                             const float* __restrict__ Wr) {
    __shared__ float swl[10 * 128];
    __shared__ float swr[10 * 128];
    int c = threadIdx.x;
    int n0 = blockIdx.x * 8;
    if (c < 8 && n0 + c < NN) g_cnt[n0 + c] = 0;
    for (int k = c; k < 10 * 128; k += 128) { swl[k] = Wl[k]; swr[k] = Wr[k]; }
    __syncthreads();
#pragma unroll
    for (int t = 0; t < 8; t++) {
        int n = n0 + t;
        if (n >= NN) break;
        float al = 0.f, ar = 0.f;
#pragma unroll
        for (int k = 0; k < 10; k++) {
            float xv = x[n * 10 + k];
            al = fmaf(xv, swl[k * 128 + c], al);
            ar = fmaf(xv, swr[k * 128 + c], ar);
        }
        g_xl1[n * 128 + c] = al;
        g_xr1[n * 128 + c] = ar;
    }
}

// ---------------- launch 2: histogram, 4 edges/thread (MLP=4 on atomics) ----------------
__global__ void k_hist(const int* __restrict__ ei) {
    int t = blockIdx.x * blockDim.x + threadIdx.x;   // t < NE/4
    if (t < NE / 4) {
        int4 d4 = *(const int4*)&ei[NE + t * 4];
        if ((unsigned)d4.x < NN) atomicAdd(&g_cnt[d4.x], 1);
        if ((unsigned)d4.y < NN) atomicAdd(&g_cnt[d4.y], 1);
        if ((unsigned)d4.z < NN) atomicAdd(&g_cnt[d4.z], 1);
        if ((unsigned)d4.w < NN) atomicAdd(&g_cnt[d4.w], 1);
    }
}

// ---------------- launch 3: per-block scan ----------------
__global__ void k_scan1() {
    __shared__ int sh[1024];
    int i = blockIdx.x * 1024 + threadIdx.x;
    int v = (i < NN) ? g_cnt[i] : 0;
    sh[threadIdx.x] = v;
    __syncthreads();
    for (int off = 1; off < 1024; off <<= 1) {
        int t = (threadIdx.x >= off) ? sh[threadIdx.x - off] : 0;
        __syncthreads();
        sh[threadIdx.x] += t;
        __syncthreads();
    }
    int incl = sh[threadIdx.x];
    if (i < NN) g_rowptr[i] = incl - v;       // block-local exclusive
    if (threadIdx.x == 1023) g_blocksum[blockIdx.x] = incl;
}

// ---------------- launch 4: finalize scan (scan2 folded in, fully parallel) ----------------
__global__ __launch_bounds__(256) void k_scan3(int nblk) {
    __shared__ int sbs[64];
    int tid = threadIdx.x;
    if (tid < 64) sbs[tid] = (tid < nblk) ? g_blocksum[tid] : 0;
    __syncthreads();
    if (tid == 0) {
        int run = 0;
#pragma unroll
        for (int b = 0; b < 64; b++) { int t = sbs[b]; sbs[b] = run; run += t; }
    }
    __syncthreads();
    int i = blockIdx.x * 256 + tid;
    if (i < NN) {
        int r = g_rowptr[i] + sbs[i >> 10];
        g_rowptr[i] = r;
        g_cnt[i] = r;       // scatter cursor
    }
    if (i == 0) g_rowptr[NN] = NE;
}

// ---------------- launch 5: scatter, 4 edges/thread (vector loads, MLP=4) ----------------
__global__ void k_scatter(const int* __restrict__ ei,
                          const float* __restrict__ edge_attr) {
    int t = blockIdx.x * blockDim.x + threadIdx.x;   // t < NE/4
    if (t < NE / 4) {
        int4   s4 = *(const int4*)&ei[t * 4];
        int4   d4 = *(const int4*)&ei[NE + t * 4];
        float4 a4 = *(const float4*)&edge_attr[t * 4];
        if ((unsigned)d4.x < NN && (unsigned)s4.x < NN) {
            int pos = atomicAdd(&g_cnt[d4.x], 1);
            g_src[pos] = s4.x; g_ea[pos] = a4.x;
        }
        if ((unsigned)d4.y < NN && (unsigned)s4.y < NN) {
            int pos = atomicAdd(&g_cnt[d4.y], 1);
            g_src[pos] = s4.y; g_ea[pos] = a4.y;
        }
        if ((unsigned)d4.z < NN && (unsigned)s4.z < NN) {
            int pos = atomicAdd(&g_cnt[d4.z], 1);
            g_src[pos] = s4.z; g_ea[pos] = a4.z;
        }
        if ((unsigned)d4.w < NN && (unsigned)s4.w < NN) {
            int pos = atomicAdd(&g_cnt[d4.w], 1);
            g_src[pos] = s4.w; g_ea[pos] = a4.w;
        }
    }
}

// ---------------- launch 6: layer-1 agg (R5 exact) ----------------
__global__ __launch_bounds__(256) void k_agg1(const float* __restrict__ att1,
                                              const float* __restrict__ W1e,
                                              const float* __restrict__ b1,
                                              const float* __restrict__ g1,
                                              const float* __restrict__ be1) {
    int warp = threadIdx.x >> 5, lane = threadIdx.x & 31;
    int node = blockIdx.x * 8 + warp;
    if (node >= NN) return;

    int cb = (lane >> 3) * 32 + (lane & 7) * 4;   // base channel (x4)

    float4 att = *(const float4*)(att1 + cb);
    float4 we  = *(const float4*)(W1e  + cb);
    float4 xli = *(const float4*)(g_xl1 + node * 128 + cb);
    float4 acc = make_float4(0.f, 0.f, 0.f, 0.f);
    float  den = 0.f;

    const float4* xr_base = (const float4*)g_xr1;   // [node][32 float4]
    int fidx = cb >> 2;

    int p0 = g_rowptr[node], p1 = g_rowptr[node + 1];
    int p = p0;
    for (; p + 1 < p1; p += 2) {
        int   s0  = g_src[p],     s1  = g_src[p + 1];
        float ea0 = g_ea[p],      ea1 = g_ea[p + 1];
        float4 xr0 = xr_base[s0 * 32 + fidx];
        float4 xr1 = xr_base[s1 * 32 + fidx];

        float t, lg0, lg1;
        t = fmaf(ea0, we.x, xli.x + xr0.x); t = fmaxf(t, 0.2f * t); lg0 = t * att.x;
        t = fmaf(ea0, we.y, xli.y + xr0.y); t = fmaxf(t, 0.2f * t); lg0 = fmaf(t, att.y, lg0);
        t = fmaf(ea0, we.z, xli.z + xr0.z); t = fmaxf(t, 0.2f * t); lg0 = fmaf(t, att.z, lg0);
        t = fmaf(ea0, we.w, xli.w + xr0.w); t = fmaxf(t, 0.2f * t); lg0 = fmaf(t, att.w, lg0);
        t = fmaf(ea1, we.x, xli.x + xr1.x); t = fmaxf(t, 0.2f * t); lg1 = t * att.x;
        t = fmaf(ea1, we.y, xli.y + xr1.y); t = fmaxf(t, 0.2f * t); lg1 = fmaf(t, att.y, lg1);
        t = fmaf(ea1, we.z, xli.z + xr1.z); t = fmaxf(t, 0.2f * t); lg1 = fmaf(t, att.z, lg1);
        t = fmaf(ea1, we.w, xli.w + xr1.w); t = fmaxf(t, 0.2f * t); lg1 = fmaf(t, att.w, lg1);

#pragma unroll
        for (int off = 4; off; off >>= 1) {
            lg0 += __shfl_xor_sync(0xffffffffu, lg0, off);
            lg1 += __shfl_xor_sync(0xffffffffu, lg1, off);
        }
        float w0 = __expf(lg0);
        float w1 = __expf(lg1);
        den += w0 + w1;
        acc.x = fmaf(w0, xr0.x, fmaf(w1, xr1.x, acc.x));
        acc.y = fmaf(w0, xr0.y, fmaf(w1, xr1.y, acc.y));
        acc.z = fmaf(w0, xr0.z, fmaf(w1, xr1.z, acc.z));
        acc.w = fmaf(w0, xr0.w, fmaf(w1, xr1.w, acc.w));
    }
    if (p < p1) {
        int   s0  = g_src[p];
        float ea0 = g_ea[p];
        float4 xr0 = xr_base[s0 * 32 + fidx];
        float t, lg0;
        t = fmaf(ea0, we.x, xli.x + xr0.x); t = fmaxf(t, 0.2f * t); lg0 = t * att.x;
        t = fmaf(ea0, we.y, xli.y + xr0.y); t = fmaxf(t, 0.2f * t); lg0 = fmaf(t, att.y, lg0);
        t = fmaf(ea0, we.z, xli.z + xr0.z); t = fmaxf(t, 0.2f * t); lg0 = fmaf(t, att.z, lg0);
        t = fmaf(ea0, we.w, xli.w + xr0.w); t = fmaxf(t, 0.2f * t); lg0 = fmaf(t, att.w, lg0);
#pragma unroll
        for (int off = 4; off; off >>= 1)
            lg0 += __shfl_xor_sync(0xffffffffu, lg0, off);
        float w0 = __expf(lg0);
        den += w0;
        acc.x = fmaf(w0, xr0.x, acc.x);
        acc.y = fmaf(w0, xr0.y, acc.y);
        acc.z = fmaf(w0, xr0.z, acc.z);
        acc.w = fmaf(w0, xr0.w, acc.w);
    }

    float inv = (den > 0.f) ? (1.f / den) : 0.f;
    float4 bb = *(const float4*)(b1 + cb);
    float o0 = acc.x * inv + bb.x;
    float o1 = acc.y * inv + bb.y;
    float o2 = acc.z * inv + bb.z;
    float o3 = acc.w * inv + bb.w;

    float s = o0 + o1 + o2 + o3;
#pragma unroll
    for (int off = 16; off; off >>= 1) s += __shfl_xor_sync(0xffffffffu, s, off);
    float mu = s * (1.f / 128.f);
    float d0 = o0 - mu, d1 = o1 - mu, d2 = o2 - mu, d3 = o3 - mu;
    float vs = fmaf(d0, d0, fmaf(d1, d1, fmaf(d2, d2, d3 * d3)));
#pragma unroll
    for (int off = 16; off; off >>= 1) vs += __shfl_xor_sync(0xffffffffu, vs, off);
    float rstd = rsqrtf(vs * (1.f / 128.f) + 1e-5f);

    float4 gg = *(const float4*)(g1  + cb);
    float4 be = *(const float4*)(be1 + cb);
    float y0 = d0 * rstd * gg.x + be.x; y0 = (y0 > 0.f) ? y0 : expm1f(y0);
    float y1 = d1 * rstd * gg.y + be.y; y1 = (y1 > 0.f) ? y1 : expm1f(y1);
    float y2 = d2 * rstd * gg.z + be.z; y2 = (y2 > 0.f) ? y2 : expm1f(y2);
    float y3 = d3 * rstd * gg.w + be.w; y3 = (y3 > 0.f) ? y3 : expm1f(y3);
    *(float4*)(g_h1 + node * 128 + cb) = make_float4(y0, y1, y2, y3);
}

// ---------------- launch 7: layer-2 dual projection (R5 exact) ----------------
__global__ __launch_bounds__(256) void k_proj2(const float* __restrict__ Wl,
                                               const float* __restrict__ Wr) {
    __shared__ float shh[32 * 128];
    __shared__ float swl[64 * 64];
    __shared__ float swr[64 * 64];
    int tid = threadIdx.x;
    int oc = tid & 63, part = tid >> 6;
    int n0 = blockIdx.x * 32;
    for (int idx = tid; idx < 32 * 128; idx += 256) {
        int n = n0 + (idx >> 7);
        shh[idx] = (n < NN) ? g_h1[n * 128 + (idx & 127)] : 0.f;
    }

    float accl[8], accr[8];
#pragma unroll
    for (int i = 0; i < 8; i++) { accl[i] = 0.f; accr[i] = 0.f; }

#pragma unroll
    for (int half = 0; half < 2; half++) {
        __syncthreads();
        for (int idx = tid; idx < 64 * 64; idx += 256) {
            swl[idx] = Wl[half * 4096 + idx];
            swr[idx] = Wr[half * 4096 + idx];
        }
        __syncthreads();
        int kb = half * 64;
#pragma unroll 4
        for (int k = 0; k < 64; k += 4) {
            float l0 = swl[(k + 0) * 64 + oc], r0 = swr[(k + 0) * 64 + oc];
            float l1 = swl[(k + 1) * 64 + oc], r1 = swr[(k + 1) * 64 + oc];
            float l2 = swl[(k + 2) * 64 + oc], r2 = swr[(k + 2) * 64 + oc];
            float l3 = swl[(k + 3) * 64 + oc], r3 = swr[(k + 3) * 64 + oc];
#pragma unroll
            for (int i = 0; i < 8; i++) {
                int nn = part + i * 4;
                float4 h4 = *(const float4*)&shh[nn * 128 + kb + k];
                accl[i] = fmaf(h4.x, l0, fmaf(h4.y, l1, fmaf(h4.z, l2, fmaf(h4.w, l3, accl[i]))));
                accr[i] = fmaf(h4.x, r0, fmaf(h4.y, r1, fmaf(h4.z, r2, fmaf(h4.w, r3, accr[i]))));
            }
        }
    }
#pragma unroll
    for (int i = 0; i < 8; i++) {
        int n = n0 + part + i * 4;
        if (n < NN) {
            g_xl2[n * 64 + oc] = accl[i];
            g_xr2[n * 64 + oc] = accr[i];
        }
    }
}

// ---------------- launch 8: layer-2 agg (R5 exact) ----------------
__global__ __launch_bounds__(256) void k_agg2(const float* __restrict__ att2,
                                              const float* __restrict__ W2e,
                                              const float* __restrict__ b2,
                                              const float* __restrict__ g2,
                                              const float* __restrict__ be2,
                                              float* __restrict__ out) {
    int warp = threadIdx.x >> 5, lane = threadIdx.x & 31;
    int node = blockIdx.x * 8 + warp;
    if (node >= NN) return;

    int cb = lane * 2;
    float2 att = *(const float2*)(att2 + cb);
    float2 we  = *(const float2*)(W2e  + cb);
    float2 xli = *(const float2*)(g_xl2 + node * 64 + cb);
    float acc0 = 0.f, acc1 = 0.f, den = 0.f;
    const float2* xr_base = (const float2*)g_xr2;

    int p0 = g_rowptr[node], p1 = g_rowptr[node + 1];
    int p = p0;
    for (; p + 1 < p1; p += 2) {
        int   s0  = g_src[p],  s1  = g_src[p + 1];
        float ea0 = g_ea[p],   ea1 = g_ea[p + 1];
        float2 xr0 = xr_base[s0 * 32 + lane];
        float2 xr1 = xr_base[s1 * 32 + lane];

        float t, lgA, lgB;
        t = fmaf(ea0, we.x, xli.x + xr0.x); t = fmaxf(t, 0.2f * t); lgA = t * att.x;
        t = fmaf(ea0, we.y, xli.y + xr0.y); t = fmaxf(t, 0.2f * t); lgA = fmaf(t, att.y, lgA);
        t = fmaf(ea1, we.x, xli.x + xr1.x); t = fmaxf(t, 0.2f * t); lgB = t * att.x;
        t = fmaf(ea1, we.y, xli.y + xr1.y); t = fmaxf(t, 0.2f * t); lgB = fmaf(t, att.y, lgB);
#pragma unroll
        for (int off = 16; off; off >>= 1) {
            lgA += __shfl_xor_sync(0xffffffffu, lgA, off);
            lgB += __shfl_xor_sync(0xffffffffu, lgB, off);
        }
        float w0 = __expf(lgA);
        float w1 = __expf(lgB);
        den += w0 + w1;
        acc0 = fmaf(w0, xr0.x, fmaf(w1, xr1.x, acc0));
        acc1 = fmaf(w0, xr0.y, fmaf(w1, xr1.y, acc1));
    }
    if (p < p1) {
        int   s0  = g_src[p];
        float ea0 = g_ea[p];
        float2 xr0 = xr_base[s0 * 32 + lane];
        float t, lgA;
        t = fmaf(ea0, we.x, xli.x + xr0.x); t = fmaxf(t, 0.2f * t); lgA = t * att.x;
        t = fmaf(ea0, we.y, xli.y + xr0.y); t = fmaxf(t, 0.2f * t); lgA = fmaf(t, att.y, lgA);
#pragma unroll
        for (int off = 16; off; off >>= 1)
            lgA += __shfl_xor_sync(0xffffffffu, lgA, off);
        float w0 = __expf(lgA);
        den += w0;
        acc0 = fmaf(w0, xr0.x, acc0);
        acc1 = fmaf(w0, xr0.y, acc1);
    }

    float inv = (den > 0.f) ? (1.f / den) : 0.f;
    float2 bb = *(const float2*)(b2 + cb);
    float o0 = acc0 * inv + bb.x;
    float o1 = acc1 * inv + bb.y;

    float s = o0 + o1;
#pragma unroll
    for (int off = 16; off; off >>= 1) s += __shfl_xor_sync(0xffffffffu, s, off);
    float mu = s * (1.f / 64.f);
    float d0 = o0 - mu, d1 = o1 - mu;
    float vs = fmaf(d0, d0, d1 * d1);
#pragma unroll
    for (int off = 16; off; off >>= 1) vs += __shfl_xor_sync(0xffffffffu, vs, off);
    float rstd = rsqrtf(vs * (1.f / 64.f) + 1e-5f);

    float2 gg = *(const float2*)(g2  + cb);
    float2 be = *(const float2*)(be2 + cb);
    float y0 = d0 * rstd * gg.x + be.x; y0 = (y0 > 0.f) ? y0 : expm1f(y0);
    float y1 = d1 * rstd * gg.y + be.y; y1 = (y1 > 0.f) ? y1 : expm1f(y1);
    *(float2*)(out + node * 64 + cb) = make_float2(y0, y1);
}

// ---------------- launcher: 8 launches ----------------
extern "C" void kernel_launch(void* const* d_in, const int* in_sizes, int n_in,
                              void* d_out, int out_size) {
    const float* x    = (const float*)d_in[0];
    const float* ea   = (const float*)d_in[1];
    const float* W1l  = (const float*)d_in[2];
    const float* W1r  = (const float*)d_in[3];
    const float* W1e  = (const float*)d_in[4];
    const float* att1 = (const float*)d_in[5];
    const float* b1   = (const float*)d_in[6];
    const float* ln1g = (const float*)d_in[7];
    const float* ln1b = (const float*)d_in[8];
    const float* W2l  = (const float*)d_in[9];
    const float* W2r  = (const float*)d_in[10];
    const float* W2e  = (const float*)d_in[11];
    const float* att2 = (const float*)d_in[12];
    const float* b2   = (const float*)d_in[13];
    const float* ln2g = (const float*)d_in[14];
    const float* ln2b = (const float*)d_in[15];
    const int*   ei   = (const int*)d_in[16];   // int32 [2, NE]
    float* out = (float*)d_out;

    const int NBLK_SCAN = (NN + 1023) / 1024;   // 49
    const int NE4 = NE / 4;                      // 200000

    k_pre    <<<(NN + 7) / 8, 128>>>(x, W1l, W1r);
    k_hist   <<<(NE4 + 255) / 256, 256>>>(ei);
    k_scan1  <<<NBLK_SCAN, 1024>>>();
    k_scan3  <<<(NN + 255) / 256, 256>>>(NBLK_SCAN);
    k_scatter<<<(NE4 + 255) / 256, 256>>>(ei, ea);
    k_agg1   <<<(NN + 7) / 8, 256>>>(att1, W1e, b1, ln1g, ln1b);
    k_proj2  <<<(NN + 31) / 32, 256>>>(W2l, W2r);
    k_agg2   <<<(NN + 7) / 8, 256>>>(att2, W2e, b2, ln2g, ln2b, out);
}

// round 13
// speedup vs baseline: 1.0881x; 1.0881x over previous
#include <cuda_runtime.h>
#include <cuda_bf16.h>
#include <math.h>

#define NN 50000
#define NE 800000

// ---------------- device scratch ----------------
__device__ float g_xl1[NN * 128];
__device__ float g_xr1[NN * 128];
__device__ float g_h1 [NN * 128];
__device__ float g_xl2[NN * 64];
__device__ float g_xr2[NN * 64];
__device__ int   g_cnt[NN];
__device__ int   g_rowptr[NN + 1];
__device__ int   g_blocksum[64];
__device__ int   g_src[NE];
__device__ float g_ea [NE];

// ---------------- launch 1: zero counters + layer-1 projections ----------------
__global__ __launch_bounds__(128) void k_pre(const float* __restrict__ x,
                                             const float* __restrict__ Wl,
                                             const float* __restrict__ Wr) {
    __shared__ float swl[10 * 128];
    __shared__ float swr[10 * 128];
    int c = threadIdx.x;
    int n0 = blockIdx.x * 8;
    if (c < 8 && n0 + c < NN) g_cnt[n0 + c] = 0;
    for (int k = c; k < 10 * 128; k += 128) { swl[k] = Wl[k]; swr[k] = Wr[k]; }
    __syncthreads();
#pragma unroll
    for (int t = 0; t < 8; t++) {
        int n = n0 + t;
        if (n >= NN) break;
        float al = 0.f, ar = 0.f;
#pragma unroll
        for (int k = 0; k < 10; k++) {
            float xv = x[n * 10 + k];
            al = fmaf(xv, swl[k * 128 + c], al);
            ar = fmaf(xv, swr[k * 128 + c], ar);
        }
        g_xl1[n * 128 + c] = al;
        g_xr1[n * 128 + c] = ar;
    }
}

// ---------------- launch 2: histogram (scalar — atomics are L2-ALU bound) ----------------
__global__ void k_hist(const int* __restrict__ ei) {
    int e = blockIdx.x * blockDim.x + threadIdx.x;
    if (e < NE) {
        unsigned dst = (unsigned)ei[NE + e];
        if (dst < NN) atomicAdd(&g_cnt[dst], 1);
    }
}

// ---------------- launch 3: per-block scan ----------------
__global__ void k_scan1() {
    __shared__ int sh[1024];
    int i = blockIdx.x * 1024 + threadIdx.x;
    int v = (i < NN) ? g_cnt[i] : 0;
    sh[threadIdx.x] = v;
    __syncthreads();
    for (int off = 1; off < 1024; off <<= 1) {
        int t = (threadIdx.x >= off) ? sh[threadIdx.x - off] : 0;
        __syncthreads();
        sh[threadIdx.x] += t;
        __syncthreads();
    }
    int incl = sh[threadIdx.x];
    if (i < NN) g_rowptr[i] = incl - v;       // block-local exclusive
    if (threadIdx.x == 1023) g_blocksum[blockIdx.x] = incl;
}

// ---------------- launch 4: finalize scan (scan2 folded in, fully parallel) ----------------
__global__ __launch_bounds__(256) void k_scan3(int nblk) {
    __shared__ int sbs[64];
    int tid = threadIdx.x;
    if (tid < 64) sbs[tid] = (tid < nblk) ? g_blocksum[tid] : 0;
    __syncthreads();
    if (tid == 0) {
        int run = 0;
#pragma unroll
        for (int b = 0; b < 64; b++) { int t = sbs[b]; sbs[b] = run; run += t; }
    }
    __syncthreads();
    int i = blockIdx.x * 256 + tid;
    if (i < NN) {
        int r = g_rowptr[i] + sbs[i >> 10];
        g_rowptr[i] = r;
        g_cnt[i] = r;       // scatter cursor
    }
    if (i == 0) g_rowptr[NN] = NE;
}

// ---------------- launch 5: scatter (scalar) ----------------
__global__ void k_scatter(const int* __restrict__ ei,
                          const float* __restrict__ edge_attr) {
    int e = blockIdx.x * blockDim.x + threadIdx.x;
    if (e < NE) {
        unsigned dst = (unsigned)ei[NE + e];
        unsigned src = (unsigned)ei[e];
        if (dst < NN && src < NN) {
            int pos = atomicAdd(&g_cnt[dst], 1);
            g_src[pos] = (int)src;
            g_ea[pos]  = edge_attr[e];
        }
    }
}

// ---------------- launch 6: layer-1 agg (R5 exact) ----------------
__global__ __launch_bounds__(256) void k_agg1(const float* __restrict__ att1,
                                              const float* __restrict__ W1e,
                                              const float* __restrict__ b1,
                                              const float* __restrict__ g1,
                                              const float* __restrict__ be1) {
    int warp = threadIdx.x >> 5, lane = threadIdx.x & 31;
    int node = blockIdx.x * 8 + warp;
    if (node >= NN) return;

    int cb = (lane >> 3) * 32 + (lane & 7) * 4;   // base channel (x4)

    float4 att = *(const float4*)(att1 + cb);
    float4 we  = *(const float4*)(W1e  + cb);
    float4 xli = *(const float4*)(g_xl1 + node * 128 + cb);
    float4 acc = make_float4(0.f, 0.f, 0.f, 0.f);
    float  den = 0.f;

    const float4* xr_base = (const float4*)g_xr1;   // [node][32 float4]
    int fidx = cb >> 2;

    int p0 = g_rowptr[node], p1 = g_rowptr[node + 1];
    int p = p0;
    for (; p + 1 < p1; p += 2) {
        int   s0  = g_src[p],     s1  = g_src[p + 1];
        float ea0 = g_ea[p],      ea1 = g_ea[p + 1];
        float4 xr0 = xr_base[s0 * 32 + fidx];
        float4 xr1 = xr_base[s1 * 32 + fidx];

        float t, lg0, lg1;
        t = fmaf(ea0, we.x, xli.x + xr0.x); t = fmaxf(t, 0.2f * t); lg0 = t * att.x;
        t = fmaf(ea0, we.y, xli.y + xr0.y); t = fmaxf(t, 0.2f * t); lg0 = fmaf(t, att.y, lg0);
        t = fmaf(ea0, we.z, xli.z + xr0.z); t = fmaxf(t, 0.2f * t); lg0 = fmaf(t, att.z, lg0);
        t = fmaf(ea0, we.w, xli.w + xr0.w); t = fmaxf(t, 0.2f * t); lg0 = fmaf(t, att.w, lg0);
        t = fmaf(ea1, we.x, xli.x + xr1.x); t = fmaxf(t, 0.2f * t); lg1 = t * att.x;
        t = fmaf(ea1, we.y, xli.y + xr1.y); t = fmaxf(t, 0.2f * t); lg1 = fmaf(t, att.y, lg1);
        t = fmaf(ea1, we.z, xli.z + xr1.z); t = fmaxf(t, 0.2f * t); lg1 = fmaf(t, att.z, lg1);
        t = fmaf(ea1, we.w, xli.w + xr1.w); t = fmaxf(t, 0.2f * t); lg1 = fmaf(t, att.w, lg1);

#pragma unroll
        for (int off = 4; off; off >>= 1) {
            lg0 += __shfl_xor_sync(0xffffffffu, lg0, off);
            lg1 += __shfl_xor_sync(0xffffffffu, lg1, off);
        }
        float w0 = __expf(lg0);
        float w1 = __expf(lg1);
        den += w0 + w1;
        acc.x = fmaf(w0, xr0.x, fmaf(w1, xr1.x, acc.x));
        acc.y = fmaf(w0, xr0.y, fmaf(w1, xr1.y, acc.y));
        acc.z = fmaf(w0, xr0.z, fmaf(w1, xr1.z, acc.z));
        acc.w = fmaf(w0, xr0.w, fmaf(w1, xr1.w, acc.w));
    }
    if (p < p1) {
        int   s0  = g_src[p];
        float ea0 = g_ea[p];
        float4 xr0 = xr_base[s0 * 32 + fidx];
        float t, lg0;
        t = fmaf(ea0, we.x, xli.x + xr0.x); t = fmaxf(t, 0.2f * t); lg0 = t * att.x;
        t = fmaf(ea0, we.y, xli.y + xr0.y); t = fmaxf(t, 0.2f * t); lg0 = fmaf(t, att.y, lg0);
        t = fmaf(ea0, we.z, xli.z + xr0.z); t = fmaxf(t, 0.2f * t); lg0 = fmaf(t, att.z, lg0);
        t = fmaf(ea0, we.w, xli.w + xr0.w); t = fmaxf(t, 0.2f * t); lg0 = fmaf(t, att.w, lg0);
#pragma unroll
        for (int off = 4; off; off >>= 1)
            lg0 += __shfl_xor_sync(0xffffffffu, lg0, off);
        float w0 = __expf(lg0);
        den += w0;
        acc.x = fmaf(w0, xr0.x, acc.x);
        acc.y = fmaf(w0, xr0.y, acc.y);
        acc.z = fmaf(w0, xr0.z, acc.z);
        acc.w = fmaf(w0, xr0.w, acc.w);
    }

    float inv = (den > 0.f) ? (1.f / den) : 0.f;
    float4 bb = *(const float4*)(b1 + cb);
    float o0 = acc.x * inv + bb.x;
    float o1 = acc.y * inv + bb.y;
    float o2 = acc.z * inv + bb.z;
    float o3 = acc.w * inv + bb.w;

    float s = o0 + o1 + o2 + o3;
#pragma unroll
    for (int off = 16; off; off >>= 1) s += __shfl_xor_sync(0xffffffffu, s, off);
    float mu = s * (1.f / 128.f);
    float d0 = o0 - mu, d1 = o1 - mu, d2 = o2 - mu, d3 = o3 - mu;
    float vs = fmaf(d0, d0, fmaf(d1, d1, fmaf(d2, d2, d3 * d3)));
#pragma unroll
    for (int off = 16; off; off >>= 1) vs += __shfl_xor_sync(0xffffffffu, vs, off);
    float rstd = rsqrtf(vs * (1.f / 128.f) + 1e-5f);

    float4 gg = *(const float4*)(g1  + cb);
    float4 be = *(const float4*)(be1 + cb);
    float y0 = d0 * rstd * gg.x + be.x; y0 = (y0 > 0.f) ? y0 : expm1f(y0);
    float y1 = d1 * rstd * gg.y + be.y; y1 = (y1 > 0.f) ? y1 : expm1f(y1);
    float y2 = d2 * rstd * gg.z + be.z; y2 = (y2 > 0.f) ? y2 : expm1f(y2);
    float y3 = d3 * rstd * gg.w + be.w; y3 = (y3 > 0.f) ? y3 : expm1f(y3);
    *(float4*)(g_h1 + node * 128 + cb) = make_float4(y0, y1, y2, y3);
}

// ---------------- launch 7: layer-2 dual projection via tf32 mma.sync (compensated) ----
// D = h1[64nodes,128] @ W[128,64], computed as hi*hi + lo*hi + hi*lo (tf32 split)
// for full fp32-level accuracy. Block: 8 warps; warp w: m-tile = (w&3)*16, matrix = w>>2.
__device__ __forceinline__ unsigned f2tf(float x) {
    unsigned r;
    asm("cvt.rna.tf32.f32 %0, %1;" : "=r"(r) : "f"(x));
    return r;
}

#define MMA_TF32(C, A0, A1, A2, A3, B0, B1)                                   \
    asm volatile("mma.sync.aligned.m16n8k8.row.col.f32.tf32.tf32.f32 "        \
                 "{%0,%1,%2,%3}, {%4,%5,%6,%7}, {%8,%9}, {%0,%1,%2,%3};"      \
                 : "+f"((C)[0]), "+f"((C)[1]), "+f"((C)[2]), "+f"((C)[3])     \
                 : "r"(A0), "r"(A1), "r"(A2), "r"(A3), "r"(B0), "r"(B1))

__global__ __launch_bounds__(256) void k_proj2(const float* __restrict__ Wl,
                                               const float* __restrict__ Wr) {
    int warp = threadIdx.x >> 5, lane = threadIdx.x & 31;
    int gid = lane >> 2, tig = lane & 3;
    const float* W    = (warp >> 2) ? Wr : Wl;
    float*       outp = (warp >> 2) ? g_xr2 : g_xl2;
    int nbase = blockIdx.x * 64 + (warp & 3) * 16;
    int row0 = nbase + gid;          // rows gid and gid+8 of the m16 tile
    int row1 = nbase + gid + 8;
    const float* h0 = g_h1 + (unsigned)min(row0, NN - 1) * 128;
    const float* h1p = g_h1 + (unsigned)min(row1, NN - 1) * 128;

    float c[8][4];
#pragma unroll
    for (int nt = 0; nt < 8; nt++)
        c[nt][0] = c[nt][1] = c[nt][2] = c[nt][3] = 0.f;

#pragma unroll
    for (int kt = 0; kt < 16; kt++) {
        int k0 = kt * 8 + tig, k1 = k0 + 4;
        float fa0 = h0[k0], fa1 = h1p[k0], fa2 = h0[k1], fa3 = h1p[k1];
        unsigned a0 = f2tf(fa0), a1 = f2tf(fa1), a2 = f2tf(fa2), a3 = f2tf(fa3);
        unsigned al0 = f2tf(fa0 - __uint_as_float(a0));
        unsigned al1 = f2tf(fa1 - __uint_as_float(a1));
        unsigned al2 = f2tf(fa2 - __uint_as_float(a2));
        unsigned al3 = f2tf(fa3 - __uint_as_float(a3));
#pragma unroll
        for (int nt = 0; nt < 8; nt++) {
            int n = nt * 8 + gid;
            float fb0 = W[k0 * 64 + n], fb1 = W[k1 * 64 + n];
            unsigned b0 = f2tf(fb0), b1 = f2tf(fb1);
            unsigned bl0 = f2tf(fb0 - __uint_as_float(b0));
            unsigned bl1 = f2tf(fb1 - __uint_as_float(b1));
            MMA_TF32(c[nt], al0, al1, al2, al3, b0, b1);    // lo * hi
            MMA_TF32(c[nt], a0, a1, a2, a3, bl0, bl1);      // hi * lo
            MMA_TF32(c[nt], a0, a1, a2, a3, b0, b1);        // hi * hi
        }
    }

#pragma unroll
    for (int nt = 0; nt < 8; nt++) {
        int col = nt * 8 + tig * 2;
        if (row0 < NN) *(float2*)&outp[row0 * 64 + col] = make_float2(c[nt][0], c[nt][1]);
        if (row1 < NN) *(float2*)&outp[row1 * 64 + col] = make_float2(c[nt][2], c[nt][3]);
    }
}

// ---------------- launch 8: layer-2 agg (R5 exact) ----------------
__global__ __launch_bounds__(256) void k_agg2(const float* __restrict__ att2,
                                              const float* __restrict__ W2e,
                                              const float* __restrict__ b2,
                                              const float* __restrict__ g2,
                                              const float* __restrict__ be2,
                                              float* __restrict__ out) {
    int warp = threadIdx.x >> 5, lane = threadIdx.x & 31;
    int node = blockIdx.x * 8 + warp;
    if (node >= NN) return;

    int cb = lane * 2;
    float2 att = *(const float2*)(att2 + cb);
    float2 we  = *(const float2*)(W2e  + cb);
    float2 xli = *(const float2*)(g_xl2 + node * 64 + cb);
    float acc0 = 0.f, acc1 = 0.f, den = 0.f;
    const float2* xr_base = (const float2*)g_xr2;

    int p0 = g_rowptr[node], p1 = g_rowptr[node + 1];
    int p = p0;
    for (; p + 1 < p1; p += 2) {
        int   s0  = g_src[p],  s1  = g_src[p + 1];
        float ea0 = g_ea[p],   ea1 = g_ea[p + 1];
        float2 xr0 = xr_base[s0 * 32 + lane];
        float2 xr1 = xr_base[s1 * 32 + lane];

        float t, lgA, lgB;
        t = fmaf(ea0, we.x, xli.x + xr0.x); t = fmaxf(t, 0.2f * t); lgA = t * att.x;
        t = fmaf(ea0, we.y, xli.y + xr0.y); t = fmaxf(t, 0.2f * t); lgA = fmaf(t, att.y, lgA);
        t = fmaf(ea1, we.x, xli.x + xr1.x); t = fmaxf(t, 0.2f * t); lgB = t * att.x;
        t = fmaf(ea1, we.y, xli.y + xr1.y); t = fmaxf(t, 0.2f * t); lgB = fmaf(t, att.y, lgB);
#pragma unroll
        for (int off = 16; off; off >>= 1) {
            lgA += __shfl_xor_sync(0xffffffffu, lgA, off);
            lgB += __shfl_xor_sync(0xffffffffu, lgB, off);
        }
        float w0 = __expf(lgA);
        float w1 = __expf(lgB);
        den += w0 + w1;
        acc0 = fmaf(w0, xr0.x, fmaf(w1, xr1.x, acc0));
        acc1 = fmaf(w0, xr0.y, fmaf(w1, xr1.y, acc1));
    }
    if (p < p1) {
        int   s0  = g_src[p];
        float ea0 = g_ea[p];
        float2 xr0 = xr_base[s0 * 32 + lane];
        float t, lgA;
        t = fmaf(ea0, we.x, xli.x + xr0.x); t = fmaxf(t, 0.2f * t); lgA = t * att.x;
        t = fmaf(ea0, we.y, xli.y + xr0.y); t = fmaxf(t, 0.2f * t); lgA = fmaf(t, att.y, lgA);
#pragma unroll
        for (int off = 16; off; off >>= 1)
            lgA += __shfl_xor_sync(0xffffffffu, lgA, off);
        float w0 = __expf(lgA);
        den += w0;
        acc0 = fmaf(w0, xr0.x, acc0);
        acc1 = fmaf(w0, xr0.y, acc1);
    }

    float inv = (den > 0.f) ? (1.f / den) : 0.f;
    float2 bb = *(const float2*)(b2 + cb);
    float o0 = acc0 * inv + bb.x;
    float o1 = acc1 * inv + bb.y;

    float s = o0 + o1;
#pragma unroll
    for (int off = 16; off; off >>= 1) s += __shfl_xor_sync(0xffffffffu, s, off);
    float mu = s * (1.f / 64.f);
    float d0 = o0 - mu, d1 = o1 - mu;
    float vs = fmaf(d0, d0, d1 * d1);
#pragma unroll
    for (int off = 16; off; off >>= 1) vs += __shfl_xor_sync(0xffffffffu, vs, off);
    float rstd = rsqrtf(vs * (1.f / 64.f) + 1e-5f);

    float2 gg = *(const float2*)(g2  + cb);
    float2 be = *(const float2*)(be2 + cb);
    float y0 = d0 * rstd * gg.x + be.x; y0 = (y0 > 0.f) ? y0 : expm1f(y0);
    float y1 = d1 * rstd * gg.y + be.y; y1 = (y1 > 0.f) ? y1 : expm1f(y1);
    *(float2*)(out + node * 64 + cb) = make_float2(y0, y1);
}

// ---------------- launcher: 8 launches ----------------
extern "C" void kernel_launch(void* const* d_in, const int* in_sizes, int n_in,
                              void* d_out, int out_size) {
    const float* x    = (const float*)d_in[0];
    const float* ea   = (const float*)d_in[1];
    const float* W1l  = (const float*)d_in[2];
    const float* W1r  = (const float*)d_in[3];
    const float* W1e  = (const float*)d_in[4];
    const float* att1 = (const float*)d_in[5];
    const float* b1   = (const float*)d_in[6];
    const float* ln1g = (const float*)d_in[7];
    const float* ln1b = (const float*)d_in[8];
    const float* W2l  = (const float*)d_in[9];
    const float* W2r  = (const float*)d_in[10];
    const float* W2e  = (const float*)d_in[11];
    const float* att2 = (const float*)d_in[12];
    const float* b2   = (const float*)d_in[13];
    const float* ln2g = (const float*)d_in[14];
    const float* ln2b = (const float*)d_in[15];
    const int*   ei   = (const int*)d_in[16];   // int32 [2, NE]
    float* out = (float*)d_out;

    const int NBLK_SCAN = (NN + 1023) / 1024;   // 49

    k_pre    <<<(NN + 7) / 8, 128>>>(x, W1l, W1r);
    k_hist   <<<(NE + 255) / 256, 256>>>(ei);
    k_scan1  <<<NBLK_SCAN, 1024>>>();
    k_scan3  <<<(NN + 255) / 256, 256>>>(NBLK_SCAN);
    k_scatter<<<(NE + 255) / 256, 256>>>(ei, ea);
    k_agg1   <<<(NN + 7) / 8, 256>>>(att1, W1e, b1, ln1g, ln1b);
    k_proj2  <<<(NN + 63) / 64, 256>>>(W2l, W2r);
    k_agg2   <<<(NN + 7) / 8, 256>>>(att2, W2e, b2, ln2g, ln2b, out);
}